// round 4
// baseline (speedup 1.0000x reference)
#include <cuda_runtime.h>
#include <cstdint>

// Radon transform: out[b, n, t] = sum_h bilinear(img_b, R(theta_n) * grid(t, h))
// B=2, N=180, H=W=512.
//
// Strategy: t-steps and h-steps are exactly 1.0 px in image space, so each
// (32 t x 32 h) chunk of samples fits in a <=46x48 px box. Stage that box in
// shared memory with coalesced float4 loads (kills the L1tex scattered-wavefront
// bottleneck), then bilinear-sample from smem with 4 LDS each.

#define IMG 512
#define NANG 180
#define NBATCH 2
#define PITCH 516                 // padded scalar image pitch (halo of zeros)
#define PAD_ELEMS (PITCH * PITCH)
#define QPR (PITCH / 4)           // 129 float4 per padded row (516*4B row is 16B-aligned)

#define TW 32                     // detector columns per block
#define CH 32                     // h steps per chunk
#define NCHUNK (IMG / CH)         // 16
#define BROWS 47                  // tile rows  (max needed 46 + slack)
#define QW 13                     // float4 per tile row
#define BCOLS (QW * 4)            // 52 floats (max needed 49 incl. alignment shift)
#define SPITCH BCOLS
#define TILE_QUADS (BROWS * QW)   // 611

__device__ float d_pad[NBATCH * PAD_ELEMS];

// Prologue: zero halo + copy image into padded buffer. Image at rows/cols [1,512].
__global__ void pad_kernel(const float* __restrict__ x) {
    int idx = blockIdx.x * blockDim.x + threadIdx.x;
    int total = NBATCH * PAD_ELEMS;
    if (idx >= total) return;
    int b   = idx / PAD_ELEMS;
    int rem = idx - b * PAD_ELEMS;
    int row = rem / PITCH;
    int col = rem - row * PITCH;
    float v = 0.0f;
    if (row >= 1 && row <= IMG && col >= 1 && col <= IMG) {
        v = x[b * (IMG * IMG) + (row - 1) * IMG + (col - 1)];
    }
    d_pad[idx] = v;
}

__global__ void __launch_bounds__(128) radon_kernel(const float* __restrict__ angles,
                                                    float* __restrict__ out) {
    __shared__ float4 tile4[TILE_QUADS];
    float* tile = (float*)tile4;

    const int tid  = threadIdx.x;
    const int warp = tid >> 5;
    const int lane = tid & 31;
    const int i = lane & 7;            // t within warp's 8-wide tile
    const int p = lane >> 3;           // h phase 0..3

    const int t_base = blockIdx.x * TW;
    const int t = t_base + warp * 8 + i;
    const int n = blockIdx.y;
    const int b = blockIdx.z;

    const float ang = angles[n] * 0.017453292519943295f;
    const float s = sinf(ang);
    const float c = cosf(ang);
    const float ns = -s;

    // Pixel coords: ix(t,h) = I0 + t*c - h*s ; iy(t,h) = J0 + t*s + h*c
    // (unit steps: 255.5 * 2/511 == 1.0 exactly)
    const float I0 = 255.5f * (s - c + 1.0f);
    const float J0 = 255.5f * (1.0f - s - c);

    const float tix0 = fmaf((float)t, c, I0);
    const float tiy0 = fmaf((float)t, s, J0);

    // block-level t extremes (for chunk bounding boxes)
    const float ix_t0 = fmaf((float)t_base, c, I0);
    const float ix_t1 = fmaf((float)(t_base + 31), c, I0);
    const float iy_t0 = fmaf((float)t_base, s, J0);
    const float iy_t1 = fmaf((float)(t_base + 31), s, J0);
    const float minAx = fminf(ix_t0, ix_t1);
    const float minAy = fminf(iy_t0, iy_t1);

    const float4* __restrict__ gquad = (const float4*)(d_pad + b * PAD_ELEMS);

    float acc = 0.0f;

    for (int chk = 0; chk < NCHUNK; ++chk) {
        const float h0 = (float)(chk * CH);
        const float h1 = (float)(chk * CH + (CH - 1));

        // min corner of the sample box (coords linear in t,h -> extremes at corners),
        // clamped like the samples will be.
        float xmn = minAx - fmaxf(h0 * s, h1 * s);
        float ymn = minAy + fminf(h0 * c, h1 * c);
        xmn = fminf(fmaxf(xmn, -1.0f), 512.0f);
        ymn = fminf(fmaxf(ymn, -1.0f), 512.0f);
        const int xmin = __float2int_rd(xmn);
        const int ymin = __float2int_rd(ymn);
        // align the tile's left edge so global float4 loads are 16B-aligned
        const int a = (xmin + 1) & 3;
        const int xminef = xmin - a;               // effective tile origin (x)
        const int base4 = (xminef + 1) >> 2;       // first float4 of each row

        __syncthreads();   // previous chunk's sampling done before overwrite
        // Fill BROWS x QW float4 tile; reads clamped into the padded image.
        for (int e = tid; e < TILE_QUADS; e += 128) {
            int r  = e / QW;
            int q  = e - r * QW;
            int gr = min(ymin + r + 1, PITCH - 1);
            int q4 = min(base4 + q, QPR - 1);
            tile4[e] = __ldg(&gquad[gr * QPR + q4]);
        }
        __syncthreads();

        const float xme = (float)xminef;
        const float yme = (float)ymin;
        const float hbase = h0 + (float)p;
        const float bix = fmaf(hbase, ns, tix0) - xme;   // relative coords
        const float biy = fmaf(hbase, c,  tiy0) - yme;
        // hi encodes the reference clamp-to-512 (rel coord xme+hi == 512);
        // the cap (50.5/45.5) only guards fp jitter, never binds legitimately.
        const float hix = fminf(512.0f - xme, 50.5f);
        const float hiy = fminf(512.0f - yme, 45.5f);

#pragma unroll
        for (int j = 0; j < CH / 4; ++j) {
            const float jf = (float)(4 * j);
            float ix = fminf(fmaxf(fmaf(jf, ns, bix), 0.0f), hix);
            float iy = fminf(fmaxf(fmaf(jf, c,  biy), 0.0f), hiy);
            const int xi = __float2int_rd(ix);
            const int yi = __float2int_rd(iy);
            const float fx = ix - (float)xi;
            const float fy = iy - (float)yi;
            const float* pp = tile + yi * SPITCH + xi;
            const float v00 = pp[0];
            const float v10 = pp[1];
            const float v01 = pp[SPITCH];
            const float v11 = pp[SPITCH + 1];
            const float top = fmaf(fx, v10 - v00, v00);
            const float bot = fmaf(fx, v11 - v01, v01);
            acc = fmaf(fy, bot - top, acc + top);
        }
    }

    // Fold the 4 h-phases (lanes p=0..3 share the same t).
    acc += __shfl_xor_sync(0xffffffffu, acc, 8);
    acc += __shfl_xor_sync(0xffffffffu, acc, 16);

    if (p == 0) {
        out[(b * NANG + n) * IMG + t] = acc;
    }
}

extern "C" void kernel_launch(void* const* d_in, const int* in_sizes, int n_in,
                              void* d_out, int out_size) {
    const float* x      = (const float*)d_in[0];   // [2,1,512,512]
    const float* angles = (const float*)d_in[1];   // [180]
    float* out          = (float*)d_out;           // [2,180,512]

    {
        int total = NBATCH * PAD_ELEMS;
        int threads = 256;
        int blocks = (total + threads - 1) / threads;
        pad_kernel<<<blocks, threads>>>(x);
    }
    {
        dim3 block(128, 1, 1);
        dim3 grid(IMG / TW, NANG, NBATCH);   // 16 x 180 x 2 = 5760 blocks
        radon_kernel<<<grid, block>>>(angles, out);
    }
}